// round 14
// baseline (speedup 1.0000x reference)
#include <cuda_runtime.h>
#include <cuda_bf16.h>
#include <math.h>
#include <stdint.h>

#define NA 15000
#define NE 300000
#define FF 128
#define NRBF 20
#define NL 3
#define CUTOFF 5.0f
#define PI_F 3.14159265358979f

// =================== static scratch ===================
__device__ float4 g_dirf[NE];                     // (dir.xyz, fcut)
__device__ __nv_bfloat16 g_phh[(size_t)NE * 32];  // padded phi hi (k20=fcut, 21..31=0)
__device__ __nv_bfloat16 g_phl[(size_t)NE * 32];  // phi lo
__device__ float g_x[NA * 384];
__device__ float g_mumix[NA * 3 * 256];
__device__ float g_dmu[NA * 384];
// bf16 hi/lo split operands
__device__ __nv_bfloat16 g_qhi[NA * 128], g_qlo[NA * 128];
__device__ __nv_bfloat16 g_hhi[NA * 128], g_hlo[NA * 128];
__device__ __nv_bfloat16 g_muhi[NA * 384], g_mulo[NA * 384];
__device__ __nv_bfloat16 g_chi[NA * 256], g_clo[NA * 256];
#define WL 180224
__device__ __nv_bfloat16 g_Bhi[NL * WL];
__device__ __nv_bfloat16 g_Blo[NL * WL];
// filter weights transposed+padded: [l][n=384][k=32]
__device__ __nv_bfloat16 g_FWh[NL * 384 * 32];
__device__ __nv_bfloat16 g_FWl[NL * 384 * 32];

__device__ __forceinline__ void split_store(__nv_bfloat16* hi, __nv_bfloat16* lo,
                                            size_t off, float v0, float v1) {
    __nv_bfloat16 h0 = __float2bfloat16(v0), h1 = __float2bfloat16(v1);
    __nv_bfloat162 H, L;
    H.x = h0; H.y = h1;
    L.x = __float2bfloat16(v0 - __bfloat162float(h0));
    L.y = __float2bfloat16(v1 - __bfloat162float(h1));
    *(__nv_bfloat162*)(hi + off) = H;
    *(__nv_bfloat162*)(lo + off) = L;
}

// =================== prep kernels ===================
__global__ void init_kernel(const int* __restrict__ z, const float* __restrict__ emb,
                            float* __restrict__ q, float* __restrict__ mu) {
    int i = blockIdx.x * blockDim.x + threadIdx.x;
    if (i >= NA * 384) return;
    mu[i] = 0.0f;
    g_dmu[i] = 0.0f;
    if (i < NA * FF) {
        int a = i >> 7, f = i & 127;
        float v = emb[z[a] * FF + f];
        q[i] = v;
        __nv_bfloat16 h = __float2bfloat16(v);
        g_qhi[i] = h;
        g_qlo[i] = __float2bfloat16(v - __bfloat162float(h));
    }
}

__global__ void geom_kernel(const float* __restrict__ rij) {
    int e = blockIdx.x * blockDim.x + threadIdx.x;
    if (e >= NE) return;
    float r0 = rij[e * 3 + 0], r1 = rij[e * 3 + 1], r2 = rij[e * 3 + 2];
    float d = sqrtf(r0 * r0 + r1 * r1 + r2 * r2);
    float inv = 1.0f / d;
    float fc = (d < CUTOFF) ? 0.5f * (cosf(d * PI_F / CUTOFF) + 1.0f) : 0.0f;
    g_dirf[e] = make_float4(r0 * inv, r1 * inv, r2 * inv, fc);
    const float width = CUTOFF / (NRBF - 1);
    const float coeff = -0.5f / (width * width);
    __nv_bfloat16* ph = g_phh + (size_t)e * 32;
    __nv_bfloat16* pl = g_phl + (size_t)e * 32;
#pragma unroll
    for (int k = 0; k < 32; k++) {
        float v;
        if (k < NRBF) {
            float t = d - width * k;
            v = expf(coeff * t * t) * fc;
        } else if (k == NRBF) {
            v = fc;
        } else {
            v = 0.0f;
        }
        __nv_bfloat16 h = __float2bfloat16(v);
        ph[k] = h;
        pl[k] = __float2bfloat16(v - __bfloat162float(h));
    }
}

__global__ void fwprep_kernel(const float* __restrict__ W, const float* __restrict__ b) {
    int i = blockIdx.x * blockDim.x + threadIdx.x;
    if (i >= NL * 384 * 32) return;
    int l = i / (384 * 32), r = i % (384 * 32);
    int n = r >> 5, k = r & 31;
    float v = 0.0f;
    if (k < NRBF) v = W[k * (NL * 384) + l * 384 + n];
    else if (k == NRBF) v = b[l * 384 + n];
    __nv_bfloat16 h = __float2bfloat16(v);
    g_FWh[i] = h;
    g_FWl[i] = __float2bfloat16(v - __bfloat162float(h));
}

__global__ void wprep_kernel(const float* __restrict__ src, int K, int N, int dstoff) {
    int i = blockIdx.x * blockDim.x + threadIdx.x;
    if (i >= NL * K * N) return;
    int l = i / (K * N), r = i % (K * N);
    int n = r / K, k = r % K;
    float v = src[(size_t)l * K * N + (size_t)k * N + n];
    __nv_bfloat16 h = __float2bfloat16(v);
    g_Bhi[l * WL + dstoff + r] = h;
    g_Blo[l * WL + dstoff + r] = __float2bfloat16(v - __bfloat162float(h));
}

// =================== mma helpers ===================
__device__ __forceinline__ void ldm_x4(uint32_t* r, uint32_t addr) {
    asm volatile("ldmatrix.sync.aligned.m8n8.x4.shared.b16 {%0,%1,%2,%3}, [%4];"
                 : "=r"(r[0]), "=r"(r[1]), "=r"(r[2]), "=r"(r[3]) : "r"(addr));
}
__device__ __forceinline__ void ldm_x2(uint32_t* r, uint32_t addr) {
    asm volatile("ldmatrix.sync.aligned.m8n8.x2.shared.b16 {%0,%1}, [%2];"
                 : "=r"(r[0]), "=r"(r[1]) : "r"(addr));
}
__device__ __forceinline__ void mma_bf16(float* d, const uint32_t* a, const uint32_t* b) {
    asm volatile(
        "mma.sync.aligned.m16n8k16.row.col.f32.bf16.bf16.f32 "
        "{%0,%1,%2,%3}, {%4,%5,%6,%7}, {%8,%9}, {%0,%1,%2,%3};"
        : "+f"(d[0]), "+f"(d[1]), "+f"(d[2]), "+f"(d[3])
        : "r"(a[0]), "r"(a[1]), "r"(a[2]), "r"(a[3]), "r"(b[0]), "r"(b[1]));
}
__device__ __forceinline__ uint32_t smem_u32(const void* p) {
    uint32_t a;
    asm("{ .reg .u64 t; cvta.to.shared.u64 t, %1; cvt.u32.u64 %0, t; }" : "=r"(a) : "l"(p));
    return a;
}

// =================== bf16x3 GEMM (atom-level, proven) ===================
#define AS 40
__global__ void __launch_bounds__(256) gemm_mma(const __nv_bfloat16* __restrict__ Ahi,
                                                const __nv_bfloat16* __restrict__ Alo,
                                                const __nv_bfloat16* __restrict__ Bhi,
                                                const __nv_bfloat16* __restrict__ Blo,
                                                const float* __restrict__ bias,
                                                float* __restrict__ C,
                                                __nv_bfloat16* __restrict__ Shi,
                                                __nv_bfloat16* __restrict__ Slo,
                                                int M, int N, int K, int act) {
    __shared__ __nv_bfloat16 sAh[128][AS], sAl[128][AS], sBh[128][AS], sBl[128][AS];
    int tid = threadIdx.x;
    int wid = tid >> 5, lane = tid & 31;
    int wm = wid & 3, wn = wid >> 2;
    int row0 = blockIdx.y * 128, col0 = blockIdx.x * 128;

    float acc[2][8][4];
#pragma unroll
    for (int i = 0; i < 2; i++)
#pragma unroll
        for (int j = 0; j < 8; j++)
#pragma unroll
            for (int k = 0; k < 4; k++) acc[i][j][k] = 0.f;

    int lrow = tid >> 1, lcol = (tid & 1) << 4;
    bool rowok = (row0 + lrow) < M;
    const __nv_bfloat16* pAh = Ahi + (size_t)(row0 + lrow) * K + lcol;
    const __nv_bfloat16* pAl = Alo + (size_t)(row0 + lrow) * K + lcol;
    const __nv_bfloat16* pBh = Bhi + (size_t)(col0 + lrow) * K + lcol;
    const __nv_bfloat16* pBl = Blo + (size_t)(col0 + lrow) * K + lcol;
    const uint4 z4 = make_uint4(0, 0, 0, 0);

    uint32_t aAh = smem_u32(&sAh[wm * 32][0]);
    uint32_t aAl = smem_u32(&sAl[wm * 32][0]);
    uint32_t aBh = smem_u32(&sBh[wn * 64][0]);
    uint32_t aBl = smem_u32(&sBl[wn * 64][0]);

    for (int c = 0; c < (K >> 5); c++) {
#pragma unroll
        for (int u = 0; u < 2; u++) {
            int co = c * 32 + u * 8;
            *(uint4*)&sAh[lrow][lcol + u * 8] = rowok ? *(const uint4*)(pAh + co) : z4;
            *(uint4*)&sAl[lrow][lcol + u * 8] = rowok ? *(const uint4*)(pAl + co) : z4;
            *(uint4*)&sBh[lrow][lcol + u * 8] = *(const uint4*)(pBh + co);
            *(uint4*)&sBl[lrow][lcol + u * 8] = *(const uint4*)(pBl + co);
        }
        __syncthreads();
#pragma unroll
        for (int ks = 0; ks < 2; ks++) {
            int kk = ks * 16;
            uint32_t ah[2][4], al[2][4];
            uint32_t aoff = ((lane & 15) * AS + kk + ((lane >> 4) << 3)) * 2;
#pragma unroll
            for (int mt = 0; mt < 2; mt++) {
                ldm_x4(ah[mt], aAh + mt * 16 * AS * 2 + aoff);
                ldm_x4(al[mt], aAl + mt * 16 * AS * 2 + aoff);
            }
            uint32_t boff = ((lane & 7) * AS + kk + (((lane >> 3) & 1) << 3)) * 2;
#pragma unroll
            for (int nt = 0; nt < 8; nt++) {
                uint32_t bh[2], bl[2];
                ldm_x2(bh, aBh + nt * 8 * AS * 2 + boff);
                ldm_x2(bl, aBl + nt * 8 * AS * 2 + boff);
#pragma unroll
                for (int mt = 0; mt < 2; mt++) {
                    mma_bf16(acc[mt][nt], ah[mt], bh);
                    mma_bf16(acc[mt][nt], ah[mt], bl);
                    mma_bf16(acc[mt][nt], al[mt], bh);
                }
            }
        }
        __syncthreads();
    }

    int gid = lane >> 2, tig = lane & 3;
#pragma unroll
    for (int mt = 0; mt < 2; mt++) {
#pragma unroll
        for (int nt = 0; nt < 8; nt++) {
            int cc = col0 + wn * 64 + nt * 8 + tig * 2;
            float b0 = __ldg(bias + cc), b1 = __ldg(bias + cc + 1);
            int r0 = row0 + wm * 32 + mt * 16 + gid;
            float v0 = acc[mt][nt][0] + b0, v1 = acc[mt][nt][1] + b1;
            float v2 = acc[mt][nt][2] + b0, v3 = acc[mt][nt][3] + b1;
            if (act) {
                v0 = v0 / (1.0f + expf(-v0));
                v1 = v1 / (1.0f + expf(-v1));
                v2 = v2 / (1.0f + expf(-v2));
                v3 = v3 / (1.0f + expf(-v3));
            }
            if (r0 < M) {
                size_t o = (size_t)r0 * N + cc;
                if (C) *(float2*)(C + o) = make_float2(v0, v1);
                if (Shi) split_store(Shi, Slo, o, v0, v1);
            }
            if (r0 + 8 < M) {
                size_t o = (size_t)(r0 + 8) * N + cc;
                if (C) *(float2*)(C + o) = make_float2(v2, v3);
                if (Shi) split_store(Shi, Slo, o, v2, v3);
            }
        }
    }
}

// =================== fused filter GEMM + smem-staged message scatter ===================
// A = padded phi (NE x 32, split), B = filter weights (384 x 32, split).
// blockIdx.x = channel (0: dq, 1: dmuR*dir, 2: dmumu*mu[j]).
// After MMA, filters staged to smem; message loop uses msg_kernel's coalesced layout.
#define FS 132                          // sF row stride (floats)
#define EDGE_SMEM (128 * FS * 4)        // 67584 B; operand tiles (40 KB) overlay low part
__global__ void __launch_bounds__(256) gemm_edge(const __nv_bfloat16* __restrict__ Ahi,
                                                 const __nv_bfloat16* __restrict__ Alo,
                                                 const __nv_bfloat16* __restrict__ Bhi,
                                                 const __nv_bfloat16* __restrict__ Blo,
                                                 const int* __restrict__ idx_i,
                                                 const int* __restrict__ idx_j,
                                                 const float* __restrict__ mu,
                                                 float* __restrict__ q) {
    extern __shared__ char sm[];
    __nv_bfloat16* sAh = (__nv_bfloat16*)sm;
    __nv_bfloat16* sAl = (__nv_bfloat16*)(sm + 10240);
    __nv_bfloat16* sBh = (__nv_bfloat16*)(sm + 20480);
    __nv_bfloat16* sBl = (__nv_bfloat16*)(sm + 30720);
    float* sF = (float*)sm;

    int tid = threadIdx.x;
    int wid = tid >> 5, lane = tid & 31;
    int wm = wid & 3, wn = wid >> 2;
    int row0 = blockIdx.y * 128;
    int chan = blockIdx.x;
    int col0 = chan * 128;

    float acc[2][8][4];
#pragma unroll
    for (int i = 0; i < 2; i++)
#pragma unroll
        for (int j = 0; j < 8; j++)
#pragma unroll
            for (int k = 0; k < 4; k++) acc[i][j][k] = 0.f;

    // load K=32 chunk
    int lrow = tid >> 1, lcol = (tid & 1) << 4;
    bool rowok = (row0 + lrow) < NE;
    const uint4 z4 = make_uint4(0, 0, 0, 0);
    {
        const __nv_bfloat16* pAh = Ahi + (size_t)(row0 + lrow) * 32 + lcol;
        const __nv_bfloat16* pAl = Alo + (size_t)(row0 + lrow) * 32 + lcol;
        const __nv_bfloat16* pBh = Bhi + (size_t)(col0 + lrow) * 32 + lcol;
        const __nv_bfloat16* pBl = Blo + (size_t)(col0 + lrow) * 32 + lcol;
        *(uint4*)(sAh + lrow * AS + lcol) = rowok ? *(const uint4*)pAh : z4;
        *(uint4*)(sAh + lrow * AS + lcol + 8) = rowok ? *(const uint4*)(pAh + 8) : z4;
        *(uint4*)(sAl + lrow * AS + lcol) = rowok ? *(const uint4*)pAl : z4;
        *(uint4*)(sAl + lrow * AS + lcol + 8) = rowok ? *(const uint4*)(pAl + 8) : z4;
        *(uint4*)(sBh + lrow * AS + lcol) = *(const uint4*)pBh;
        *(uint4*)(sBh + lrow * AS + lcol + 8) = *(const uint4*)(pBh + 8);
        *(uint4*)(sBl + lrow * AS + lcol) = *(const uint4*)pBl;
        *(uint4*)(sBl + lrow * AS + lcol + 8) = *(const uint4*)(pBl + 8);
    }
    __syncthreads();
    {
        uint32_t aAh = smem_u32(sAh + wm * 32 * AS);
        uint32_t aAl = smem_u32(sAl + wm * 32 * AS);
        uint32_t aBh = smem_u32(sBh + wn * 64 * AS);
        uint32_t aBl = smem_u32(sBl + wn * 64 * AS);
#pragma unroll
        for (int ks = 0; ks < 2; ks++) {
            int kk = ks * 16;
            uint32_t ah[2][4], al[2][4];
            uint32_t aoff = ((lane & 15) * AS + kk + ((lane >> 4) << 3)) * 2;
#pragma unroll
            for (int mt = 0; mt < 2; mt++) {
                ldm_x4(ah[mt], aAh + mt * 16 * AS * 2 + aoff);
                ldm_x4(al[mt], aAl + mt * 16 * AS * 2 + aoff);
            }
            uint32_t boff = ((lane & 7) * AS + kk + (((lane >> 3) & 1) << 3)) * 2;
#pragma unroll
            for (int nt = 0; nt < 8; nt++) {
                uint32_t bh[2], bl[2];
                ldm_x2(bh, aBh + nt * 8 * AS * 2 + boff);
                ldm_x2(bl, aBl + nt * 8 * AS * 2 + boff);
#pragma unroll
                for (int mt = 0; mt < 2; mt++) {
                    mma_bf16(acc[mt][nt], ah[mt], bh);
                    mma_bf16(acc[mt][nt], ah[mt], bl);
                    mma_bf16(acc[mt][nt], al[mt], bh);
                }
            }
        }
    }
    __syncthreads();  // all ldmatrix reads done; safe to overlay sF

    // stage filters to smem (local edge el, local feature fl)
    {
        int gid = lane >> 2, tig = lane & 3;
#pragma unroll
        for (int mt = 0; mt < 2; mt++) {
            int el = wm * 32 + mt * 16 + gid;
#pragma unroll
            for (int nt = 0; nt < 8; nt++) {
                int fl = wn * 64 + nt * 8 + tig * 2;
                *(float2*)&sF[el * FS + fl] = make_float2(acc[mt][nt][0], acc[mt][nt][1]);
                *(float2*)&sF[(el + 8) * FS + fl] = make_float2(acc[mt][nt][2], acc[mt][nt][3]);
            }
        }
    }
    __syncthreads();

    // coalesced message scatter (msg_kernel layout: f = tid&127, 2 edge lanes)
    int f = tid & 127;
    int par = tid >> 7;
    for (int t = par; t < 128; t += 2) {
        int e = row0 + t;
        if (e >= NE) break;
        int i = __ldg(idx_i + e), j = __ldg(idx_j + e);
        float F = sF[t * FS + f];
        if (chan == 0) {
            float dq = F * __ldg(g_x + j * 384 + f);
            atomicAdd(q + i * 128 + f, dq);
        } else if (chan == 1) {
            float4 df = __ldg(g_dirf + e);
            float v = F * __ldg(g_x + j * 384 + 128 + f);
            float* di = g_dmu + i * 384;
            atomicAdd(di + f, v * df.x);
            atomicAdd(di + 128 + f, v * df.y);
            atomicAdd(di + 256 + f, v * df.z);
        } else {
            float v = F * __ldg(g_x + j * 384 + 256 + f);
            const float* mj = mu + j * 384;
            float* di = g_dmu + i * 384;
            atomicAdd(di + f, v * __ldg(mj + f));
            atomicAdd(di + 128 + f, v * __ldg(mj + 128 + f));
            atomicAdd(di + 256 + f, v * __ldg(mj + 256 + f));
        }
    }
}

// mu += dmu; dmu = 0; emit mu hi/lo split
__global__ void addmu_kernel(float* __restrict__ mu) {
    int i = (blockIdx.x * blockDim.x + threadIdx.x) * 2;
    if (i >= NA * 384) return;
    float v0 = mu[i] + g_dmu[i];
    float v1 = mu[i + 1] + g_dmu[i + 1];
    mu[i] = v0;
    mu[i + 1] = v1;
    g_dmu[i] = 0.0f;
    g_dmu[i + 1] = 0.0f;
    split_store(g_muhi, g_mulo, i, v0, v1);
}

// =================== ctx / update ===================
__global__ void ctx_kernel(const float* __restrict__ q) {
    int i = (blockIdx.x * blockDim.x + threadIdx.x) * 2;
    if (i >= NA * FF) return;
    int a = i >> 7, f = i & 127;
    float v0 = g_mumix[(a * 3 + 0) * 256 + f];
    float v1 = g_mumix[(a * 3 + 1) * 256 + f];
    float v2 = g_mumix[(a * 3 + 2) * 256 + f];
    float n0 = sqrtf(v0 * v0 + v1 * v1 + v2 * v2);
    float u0 = g_mumix[(a * 3 + 0) * 256 + f + 1];
    float u1 = g_mumix[(a * 3 + 1) * 256 + f + 1];
    float u2 = g_mumix[(a * 3 + 2) * 256 + f + 1];
    float n1 = sqrtf(u0 * u0 + u1 * u1 + u2 * u2);
    split_store(g_chi, g_clo, (size_t)a * 256 + f, q[i], q[i + 1]);
    split_store(g_chi, g_clo, (size_t)a * 256 + 128 + f, n0, n1);
}

__global__ void update_kernel(float* __restrict__ q, float* __restrict__ mu) {
    int i = (blockIdx.x * blockDim.x + threadIdx.x) * 2;
    if (i >= NA * FF) return;
    int a = i >> 7, f = i & 127;
    float s0 = 0.0f, s1 = 0.0f;
    float xmu0 = g_x[a * 384 + 128 + f], xmu1 = g_x[a * 384 + 128 + f + 1];
#pragma unroll
    for (int d = 0; d < 3; d++) {
        float mv0 = g_mumix[(a * 3 + d) * 256 + f];
        float mw0 = g_mumix[(a * 3 + d) * 256 + 128 + f];
        float mv1 = g_mumix[(a * 3 + d) * 256 + f + 1];
        float mw1 = g_mumix[(a * 3 + d) * 256 + 128 + f + 1];
        s0 += mv0 * mw0;
        s1 += mv1 * mw1;
        mu[a * 384 + d * 128 + f] += xmu0 * mw0;
        mu[a * 384 + d * 128 + f + 1] += xmu1 * mw1;
    }
    float q0 = q[i] + g_x[a * 384 + f] + g_x[a * 384 + 256 + f] * s0;
    float q1 = q[i + 1] + g_x[a * 384 + f + 1] + g_x[a * 384 + 256 + f + 1] * s1;
    q[i] = q0;
    q[i + 1] = q1;
    split_store(g_qhi, g_qlo, i, q0, q1);
}

// =================== launcher ===================
extern "C" void kernel_launch(void* const* d_in, const int* in_sizes, int n_in,
                              void* d_out, int out_size) {
    const float* r_ij      = (const float*)d_in[0];
    const float* embedding = (const float*)d_in[1];
    const float* filt_W    = (const float*)d_in[2];
    const float* filt_b    = (const float*)d_in[3];
    const float* inter_W1  = (const float*)d_in[4];
    const float* inter_b1  = (const float*)d_in[5];
    const float* inter_W2  = (const float*)d_in[6];
    const float* inter_b2  = (const float*)d_in[7];
    const float* mix_W     = (const float*)d_in[8];
    const float* mix_b     = (const float*)d_in[9];
    const float* intra_W1  = (const float*)d_in[10];
    const float* intra_b1  = (const float*)d_in[11];
    const float* intra_W2  = (const float*)d_in[12];
    const float* intra_b2  = (const float*)d_in[13];
    const int*   z         = (const int*)d_in[14];
    const int*   idx_i     = (const int*)d_in[15];
    const int*   idx_j     = (const int*)d_in[16];

    float* q  = (float*)d_out;
    float* mu = q + (size_t)NA * FF;

    cudaFuncSetAttribute(gemm_edge, cudaFuncAttributeMaxDynamicSharedMemorySize, EDGE_SMEM);

    void *p_x, *p_mumix, *p_qhi, *p_qlo, *p_hhi, *p_hlo, *p_muhi, *p_mulo, *p_chi, *p_clo,
        *p_Bhi, *p_Blo, *p_FWh, *p_FWl, *p_phh, *p_phl;
    cudaGetSymbolAddress(&p_x, g_x);
    cudaGetSymbolAddress(&p_mumix, g_mumix);
    cudaGetSymbolAddress(&p_qhi, g_qhi);
    cudaGetSymbolAddress(&p_qlo, g_qlo);
    cudaGetSymbolAddress(&p_hhi, g_hhi);
    cudaGetSymbolAddress(&p_hlo, g_hlo);
    cudaGetSymbolAddress(&p_muhi, g_muhi);
    cudaGetSymbolAddress(&p_mulo, g_mulo);
    cudaGetSymbolAddress(&p_chi, g_chi);
    cudaGetSymbolAddress(&p_clo, g_clo);
    cudaGetSymbolAddress(&p_Bhi, g_Bhi);
    cudaGetSymbolAddress(&p_Blo, g_Blo);
    cudaGetSymbolAddress(&p_FWh, g_FWh);
    cudaGetSymbolAddress(&p_FWl, g_FWl);
    cudaGetSymbolAddress(&p_phh, g_phh);
    cudaGetSymbolAddress(&p_phl, g_phl);
    float* xbuf  = (float*)p_x;
    float* mumix = (float*)p_mumix;
    __nv_bfloat16 *qhi = (__nv_bfloat16*)p_qhi, *qlo = (__nv_bfloat16*)p_qlo;
    __nv_bfloat16 *hhi = (__nv_bfloat16*)p_hhi, *hlo = (__nv_bfloat16*)p_hlo;
    __nv_bfloat16 *muhi = (__nv_bfloat16*)p_muhi, *mulo = (__nv_bfloat16*)p_mulo;
    __nv_bfloat16 *chi = (__nv_bfloat16*)p_chi, *clo = (__nv_bfloat16*)p_clo;
    __nv_bfloat16 *Bhi = (__nv_bfloat16*)p_Bhi, *Blo = (__nv_bfloat16*)p_Blo;
    __nv_bfloat16 *FWh = (__nv_bfloat16*)p_FWh, *FWl = (__nv_bfloat16*)p_FWl;
    __nv_bfloat16 *phh = (__nv_bfloat16*)p_phh, *phl = (__nv_bfloat16*)p_phl;

    init_kernel<<<(NA * 384 + 255) / 256, 256>>>(z, embedding, q, mu);
    geom_kernel<<<(NE + 255) / 256, 256>>>(r_ij);
    fwprep_kernel<<<(NL * 384 * 32 + 255) / 256, 256>>>(filt_W, filt_b);
    wprep_kernel<<<(NL * 128 * 128 + 255) / 256, 256>>>(inter_W1, 128, 128, 0);
    wprep_kernel<<<(NL * 128 * 384 + 255) / 256, 256>>>(inter_W2, 128, 384, 16384);
    wprep_kernel<<<(NL * 128 * 256 + 255) / 256, 256>>>(mix_W, 128, 256, 65536);
    wprep_kernel<<<(NL * 256 * 128 + 255) / 256, 256>>>(intra_W1, 256, 128, 98304);
    wprep_kernel<<<(NL * 128 * 384 + 255) / 256, 256>>>(intra_W2, 128, 384, 131072);

    for (int l = 0; l < NL; l++) {
        int wb = l * WL;
        // h = silu(q @ W1 + b1) -> split only
        gemm_mma<<<dim3(1, (NA + 127) / 128), 256>>>(
            qhi, qlo, Bhi + wb, Blo + wb, inter_b1 + l * 128,
            nullptr, hhi, hlo, NA, 128, 128, 1);
        // x = h @ W2 + b2 -> fp32
        gemm_mma<<<dim3(3, (NA + 127) / 128), 256>>>(
            hhi, hlo, Bhi + wb + 16384, Blo + wb + 16384, inter_b2 + l * 384,
            xbuf, nullptr, nullptr, NA, 384, 128, 0);
        // fused filter GEMM + smem-staged message scatter
        gemm_edge<<<dim3(3, (NE + 127) / 128), 256, EDGE_SMEM>>>(
            phh, phl, FWh + l * 12288, FWl + l * 12288, idx_i, idx_j, mu, q);
        // mu += dmu (emit mu split)
        addmu_kernel<<<(NA * 192 + 255) / 256, 256>>>(mu);
        // mu_mix = mu @ mix_W + mix_b -> fp32
        gemm_mma<<<dim3(2, (NA * 3 + 127) / 128), 256>>>(
            muhi, mulo, Bhi + wb + 65536, Blo + wb + 65536, mix_b + l * 256,
            mumix, nullptr, nullptr, NA * 3, 256, 128, 0);
        // ctx = [q, ||mu_V||] -> split only
        ctx_kernel<<<(NA * 64 + 255) / 256, 256>>>(q);
        // h = silu(ctx @ intra_W1 + b1) -> split only
        gemm_mma<<<dim3(1, (NA + 127) / 128), 256>>>(
            chi, clo, Bhi + wb + 98304, Blo + wb + 98304, intra_b1 + l * 128,
            nullptr, hhi, hlo, NA, 128, 256, 1);
        // x = h @ intra_W2 + b2 -> fp32
        gemm_mma<<<dim3(3, (NA + 127) / 128), 256>>>(
            hhi, hlo, Bhi + wb + 131072, Blo + wb + 131072, intra_b2 + l * 384,
            xbuf, nullptr, nullptr, NA, 384, 128, 0);
        // q += dq_intra + dqmu_intra (emit q split); mu += dmu_intra
        update_kernel<<<(NA * 64 + 255) / 256, 256>>>(q, mu);
    }
}

// round 15
// speedup vs baseline: 1.3690x; 1.3690x over previous
#include <cuda_runtime.h>
#include <cuda_bf16.h>
#include <math.h>
#include <stdint.h>

#define NA 15000
#define NE 300000
#define FF 128
#define NRBF 20
#define NL 3
#define CUTOFF 5.0f
#define PI_F 3.14159265358979f

// =================== static scratch ===================
__device__ float4 g_dirf[NE];                     // SORTED (dir.xyz, fcut)
__device__ __nv_bfloat16 g_phh[(size_t)NE * 32];  // SORTED padded phi hi (k20=fcut)
__device__ __nv_bfloat16 g_phl[(size_t)NE * 32];  // SORTED phi lo
__device__ float g_filt[(size_t)NE * 384];        // SORTED per-edge filters (fp32)
__device__ int g_is[NE], g_js[NE], g_perm[NE];
__device__ int g_cnt[NA], g_head[NA];
__device__ float g_x[NA * 384];
__device__ float g_mumix[NA * 3 * 256];
__device__ float g_dmu[NA * 384];
__device__ float g_zeros[384];
// bf16 hi/lo split operands
__device__ __nv_bfloat16 g_qhi[NA * 128], g_qlo[NA * 128];
__device__ __nv_bfloat16 g_hhi[NA * 128], g_hlo[NA * 128];
__device__ __nv_bfloat16 g_muhi[NA * 384], g_mulo[NA * 384];
__device__ __nv_bfloat16 g_chi[NA * 256], g_clo[NA * 256];
#define WL 180224
__device__ __nv_bfloat16 g_Bhi[NL * WL];
__device__ __nv_bfloat16 g_Blo[NL * WL];
// filter weights transposed+padded: [l][n=384][k=32]
__device__ __nv_bfloat16 g_FWh[NL * 384 * 32];
__device__ __nv_bfloat16 g_FWl[NL * 384 * 32];

__device__ __forceinline__ void split_store(__nv_bfloat16* hi, __nv_bfloat16* lo,
                                            size_t off, float v0, float v1) {
    __nv_bfloat16 h0 = __float2bfloat16(v0), h1 = __float2bfloat16(v1);
    __nv_bfloat162 H, L;
    H.x = h0; H.y = h1;
    L.x = __float2bfloat16(v0 - __bfloat162float(h0));
    L.y = __float2bfloat16(v1 - __bfloat162float(h1));
    *(__nv_bfloat162*)(hi + off) = H;
    *(__nv_bfloat162*)(lo + off) = L;
}

// =================== prep kernels ===================
__global__ void init_kernel(const int* __restrict__ z, const float* __restrict__ emb,
                            float* __restrict__ q, float* __restrict__ mu) {
    int i = blockIdx.x * blockDim.x + threadIdx.x;
    if (i >= NA * 384) return;
    mu[i] = 0.0f;
    g_dmu[i] = 0.0f;
    if (i < NA) g_cnt[i] = 0;
    if (i < NA * FF) {
        int a = i >> 7, f = i & 127;
        float v = emb[z[a] * FF + f];
        q[i] = v;
        __nv_bfloat16 h = __float2bfloat16(v);
        g_qhi[i] = h;
        g_qlo[i] = __float2bfloat16(v - __bfloat162float(h));
    }
}

__global__ void hist_kernel(const int* __restrict__ idx_i) {
    int e = blockIdx.x * blockDim.x + threadIdx.x;
    if (e < NE) atomicAdd(&g_cnt[idx_i[e]], 1);
}

#define SCAN_T 1024
#define SCAN_CH ((NA + SCAN_T - 1) / SCAN_T)
__global__ void __launch_bounds__(SCAN_T) scan_kernel() {
    __shared__ int sh[SCAN_T];
    int t = threadIdx.x;
    int start = t * SCAN_CH;
    int s = 0;
#pragma unroll
    for (int k = 0; k < SCAN_CH; k++) {
        int i = start + k;
        if (i < NA) s += g_cnt[i];
    }
    sh[t] = s;
    __syncthreads();
    for (int off = 1; off < SCAN_T; off <<= 1) {
        int v = (t >= off) ? sh[t - off] : 0;
        __syncthreads();
        sh[t] += v;
        __syncthreads();
    }
    int base = (t == 0) ? 0 : sh[t - 1];
#pragma unroll
    for (int k = 0; k < SCAN_CH; k++) {
        int i = start + k;
        if (i < NA) {
            g_head[i] = base;
            base += g_cnt[i];
        }
    }
}

__global__ void scatter_kernel(const int* __restrict__ idx_i, const int* __restrict__ idx_j) {
    int e = blockIdx.x * blockDim.x + threadIdx.x;
    if (e >= NE) return;
    int i = idx_i[e];
    int pos = atomicAdd(&g_head[i], 1);
    g_perm[e] = pos;
    g_is[pos] = i;
    g_js[pos] = idx_j[e];
}

// geometry written at SORTED positions: dirf + padded split phi (k20 = fcut = bias row)
__global__ void geom_kernel(const float* __restrict__ rij) {
    int e = blockIdx.x * blockDim.x + threadIdx.x;
    if (e >= NE) return;
    int p = g_perm[e];
    float r0 = rij[e * 3 + 0], r1 = rij[e * 3 + 1], r2 = rij[e * 3 + 2];
    float d = sqrtf(r0 * r0 + r1 * r1 + r2 * r2);
    float inv = 1.0f / d;
    float fc = (d < CUTOFF) ? 0.5f * (cosf(d * PI_F / CUTOFF) + 1.0f) : 0.0f;
    g_dirf[p] = make_float4(r0 * inv, r1 * inv, r2 * inv, fc);
    const float width = CUTOFF / (NRBF - 1);
    const float coeff = -0.5f / (width * width);
    __nv_bfloat16* ph = g_phh + (size_t)p * 32;
    __nv_bfloat16* pl = g_phl + (size_t)p * 32;
#pragma unroll
    for (int k = 0; k < 32; k++) {
        float v;
        if (k < NRBF) {
            float t = d - width * k;
            v = expf(coeff * t * t) * fc;
        } else if (k == NRBF) {
            v = fc;
        } else {
            v = 0.0f;
        }
        __nv_bfloat16 h = __float2bfloat16(v);
        ph[k] = h;
        pl[k] = __float2bfloat16(v - __bfloat162float(h));
    }
}

__global__ void fwprep_kernel(const float* __restrict__ W, const float* __restrict__ b) {
    int i = blockIdx.x * blockDim.x + threadIdx.x;
    if (i >= NL * 384 * 32) return;
    int l = i / (384 * 32), r = i % (384 * 32);
    int n = r >> 5, k = r & 31;
    float v = 0.0f;
    if (k < NRBF) v = W[k * (NL * 384) + l * 384 + n];
    else if (k == NRBF) v = b[l * 384 + n];
    __nv_bfloat16 h = __float2bfloat16(v);
    g_FWh[i] = h;
    g_FWl[i] = __float2bfloat16(v - __bfloat162float(h));
}

__global__ void wprep_kernel(const float* __restrict__ src, int K, int N, int dstoff) {
    int i = blockIdx.x * blockDim.x + threadIdx.x;
    if (i >= NL * K * N) return;
    int l = i / (K * N), r = i % (K * N);
    int n = r / K, k = r % K;
    float v = src[(size_t)l * K * N + (size_t)k * N + n];
    __nv_bfloat16 h = __float2bfloat16(v);
    g_Bhi[l * WL + dstoff + r] = h;
    g_Blo[l * WL + dstoff + r] = __float2bfloat16(v - __bfloat162float(h));
}

// =================== mma helpers ===================
__device__ __forceinline__ void ldm_x4(uint32_t* r, uint32_t addr) {
    asm volatile("ldmatrix.sync.aligned.m8n8.x4.shared.b16 {%0,%1,%2,%3}, [%4];"
                 : "=r"(r[0]), "=r"(r[1]), "=r"(r[2]), "=r"(r[3]) : "r"(addr));
}
__device__ __forceinline__ void ldm_x2(uint32_t* r, uint32_t addr) {
    asm volatile("ldmatrix.sync.aligned.m8n8.x2.shared.b16 {%0,%1}, [%2];"
                 : "=r"(r[0]), "=r"(r[1]) : "r"(addr));
}
__device__ __forceinline__ void mma_bf16(float* d, const uint32_t* a, const uint32_t* b) {
    asm volatile(
        "mma.sync.aligned.m16n8k16.row.col.f32.bf16.bf16.f32 "
        "{%0,%1,%2,%3}, {%4,%5,%6,%7}, {%8,%9}, {%0,%1,%2,%3};"
        : "+f"(d[0]), "+f"(d[1]), "+f"(d[2]), "+f"(d[3])
        : "r"(a[0]), "r"(a[1]), "r"(a[2]), "r"(a[3]), "r"(b[0]), "r"(b[1]));
}
__device__ __forceinline__ uint32_t smem_u32(const void* p) {
    uint32_t a;
    asm("{ .reg .u64 t; cvta.to.shared.u64 t, %1; cvt.u32.u64 %0, t; }" : "=r"(a) : "l"(p));
    return a;
}

// =================== bf16x3 GEMM (proven) ===================
#define AS 40
__global__ void __launch_bounds__(256) gemm_mma(const __nv_bfloat16* __restrict__ Ahi,
                                                const __nv_bfloat16* __restrict__ Alo,
                                                const __nv_bfloat16* __restrict__ Bhi,
                                                const __nv_bfloat16* __restrict__ Blo,
                                                const float* __restrict__ bias,
                                                float* __restrict__ C,
                                                __nv_bfloat16* __restrict__ Shi,
                                                __nv_bfloat16* __restrict__ Slo,
                                                int M, int N, int K, int act) {
    __shared__ __nv_bfloat16 sAh[128][AS], sAl[128][AS], sBh[128][AS], sBl[128][AS];
    int tid = threadIdx.x;
    int wid = tid >> 5, lane = tid & 31;
    int wm = wid & 3, wn = wid >> 2;
    int row0 = blockIdx.y * 128, col0 = blockIdx.x * 128;

    float acc[2][8][4];
#pragma unroll
    for (int i = 0; i < 2; i++)
#pragma unroll
        for (int j = 0; j < 8; j++)
#pragma unroll
            for (int k = 0; k < 4; k++) acc[i][j][k] = 0.f;

    int lrow = tid >> 1, lcol = (tid & 1) << 4;
    bool rowok = (row0 + lrow) < M;
    const __nv_bfloat16* pAh = Ahi + (size_t)(row0 + lrow) * K + lcol;
    const __nv_bfloat16* pAl = Alo + (size_t)(row0 + lrow) * K + lcol;
    const __nv_bfloat16* pBh = Bhi + (size_t)(col0 + lrow) * K + lcol;
    const __nv_bfloat16* pBl = Blo + (size_t)(col0 + lrow) * K + lcol;
    const uint4 z4 = make_uint4(0, 0, 0, 0);

    uint32_t aAh = smem_u32(&sAh[wm * 32][0]);
    uint32_t aAl = smem_u32(&sAl[wm * 32][0]);
    uint32_t aBh = smem_u32(&sBh[wn * 64][0]);
    uint32_t aBl = smem_u32(&sBl[wn * 64][0]);

    for (int c = 0; c < (K >> 5); c++) {
#pragma unroll
        for (int u = 0; u < 2; u++) {
            int co = c * 32 + u * 8;
            *(uint4*)&sAh[lrow][lcol + u * 8] = rowok ? *(const uint4*)(pAh + co) : z4;
            *(uint4*)&sAl[lrow][lcol + u * 8] = rowok ? *(const uint4*)(pAl + co) : z4;
            *(uint4*)&sBh[lrow][lcol + u * 8] = *(const uint4*)(pBh + co);
            *(uint4*)&sBl[lrow][lcol + u * 8] = *(const uint4*)(pBl + co);
        }
        __syncthreads();
#pragma unroll
        for (int ks = 0; ks < 2; ks++) {
            int kk = ks * 16;
            uint32_t ah[2][4], al[2][4];
            uint32_t aoff = ((lane & 15) * AS + kk + ((lane >> 4) << 3)) * 2;
#pragma unroll
            for (int mt = 0; mt < 2; mt++) {
                ldm_x4(ah[mt], aAh + mt * 16 * AS * 2 + aoff);
                ldm_x4(al[mt], aAl + mt * 16 * AS * 2 + aoff);
            }
            uint32_t boff = ((lane & 7) * AS + kk + (((lane >> 3) & 1) << 3)) * 2;
#pragma unroll
            for (int nt = 0; nt < 8; nt++) {
                uint32_t bh[2], bl[2];
                ldm_x2(bh, aBh + nt * 8 * AS * 2 + boff);
                ldm_x2(bl, aBl + nt * 8 * AS * 2 + boff);
#pragma unroll
                for (int mt = 0; mt < 2; mt++) {
                    mma_bf16(acc[mt][nt], ah[mt], bh);
                    mma_bf16(acc[mt][nt], ah[mt], bl);
                    mma_bf16(acc[mt][nt], al[mt], bh);
                }
            }
        }
        __syncthreads();
    }

    int gid = lane >> 2, tig = lane & 3;
#pragma unroll
    for (int mt = 0; mt < 2; mt++) {
#pragma unroll
        for (int nt = 0; nt < 8; nt++) {
            int cc = col0 + wn * 64 + nt * 8 + tig * 2;
            float b0 = __ldg(bias + cc), b1 = __ldg(bias + cc + 1);
            int r0 = row0 + wm * 32 + mt * 16 + gid;
            float v0 = acc[mt][nt][0] + b0, v1 = acc[mt][nt][1] + b1;
            float v2 = acc[mt][nt][2] + b0, v3 = acc[mt][nt][3] + b1;
            if (act) {
                v0 = v0 / (1.0f + expf(-v0));
                v1 = v1 / (1.0f + expf(-v1));
                v2 = v2 / (1.0f + expf(-v2));
                v3 = v3 / (1.0f + expf(-v3));
            }
            if (r0 < M) {
                size_t o = (size_t)r0 * N + cc;
                if (C) *(float2*)(C + o) = make_float2(v0, v1);
                if (Shi) split_store(Shi, Slo, o, v0, v1);
            }
            if (r0 + 8 < M) {
                size_t o = (size_t)(r0 + 8) * N + cc;
                if (C) *(float2*)(C + o) = make_float2(v2, v3);
                if (Shi) split_store(Shi, Slo, o, v2, v3);
            }
        }
    }
}

// =================== message kernel (sorted chunks, register accumulation) ===================
// Edges sorted by destination atom i. Each block owns a contiguous 128-edge chunk;
// dq/dmu accumulate in registers, atomics fire only when the atom changes.
__global__ void __launch_bounds__(128) msg_kernel(const float* __restrict__ F,
                                                  const float* __restrict__ mu,
                                                  float* __restrict__ q) {
    int f = threadIdx.x;
    int base = blockIdx.x * 128;
    int eend = min(base + 128, NE);
    float aq = 0.f, a0 = 0.f, a1 = 0.f, a2 = 0.f;
    int curi = -1;
#pragma unroll 2
    for (int e = base; e < eend; e++) {
        int i = __ldg(g_is + e);
        if (i != curi) {
            if (curi >= 0) {
                atomicAdd(q + curi * 128 + f, aq);
                atomicAdd(g_dmu + curi * 384 + f, a0);
                atomicAdd(g_dmu + curi * 384 + 128 + f, a1);
                atomicAdd(g_dmu + curi * 384 + 256 + f, a2);
            }
            curi = i;
            aq = a0 = a1 = a2 = 0.f;
        }
        int j = __ldg(g_js + e);
        const float* Fe = F + (size_t)e * 384;
        float F0 = __ldg(Fe + f), F1 = __ldg(Fe + 128 + f), F2 = __ldg(Fe + 256 + f);
        float4 df = __ldg(g_dirf + e);
        const float* xj = g_x + j * 384;
        const float* mj = mu + j * 384;
        float dmuR = F1 * __ldg(xj + 128 + f);
        float dmm  = F2 * __ldg(xj + 256 + f);
        aq += F0 * __ldg(xj + f);
        a0 += dmuR * df.x + dmm * __ldg(mj + f);
        a1 += dmuR * df.y + dmm * __ldg(mj + 128 + f);
        a2 += dmuR * df.z + dmm * __ldg(mj + 256 + f);
    }
    if (curi >= 0) {
        atomicAdd(q + curi * 128 + f, aq);
        atomicAdd(g_dmu + curi * 384 + f, a0);
        atomicAdd(g_dmu + curi * 384 + 128 + f, a1);
        atomicAdd(g_dmu + curi * 384 + 256 + f, a2);
    }
}

// mu += dmu; dmu = 0; emit mu hi/lo split
__global__ void addmu_kernel(float* __restrict__ mu) {
    int i = (blockIdx.x * blockDim.x + threadIdx.x) * 2;
    if (i >= NA * 384) return;
    float v0 = mu[i] + g_dmu[i];
    float v1 = mu[i + 1] + g_dmu[i + 1];
    mu[i] = v0;
    mu[i + 1] = v1;
    g_dmu[i] = 0.0f;
    g_dmu[i + 1] = 0.0f;
    split_store(g_muhi, g_mulo, i, v0, v1);
}

// =================== ctx / update ===================
__global__ void ctx_kernel(const float* __restrict__ q) {
    int i = (blockIdx.x * blockDim.x + threadIdx.x) * 2;
    if (i >= NA * FF) return;
    int a = i >> 7, f = i & 127;
    float v0 = g_mumix[(a * 3 + 0) * 256 + f];
    float v1 = g_mumix[(a * 3 + 1) * 256 + f];
    float v2 = g_mumix[(a * 3 + 2) * 256 + f];
    float n0 = sqrtf(v0 * v0 + v1 * v1 + v2 * v2);
    float u0 = g_mumix[(a * 3 + 0) * 256 + f + 1];
    float u1 = g_mumix[(a * 3 + 1) * 256 + f + 1];
    float u2 = g_mumix[(a * 3 + 2) * 256 + f + 1];
    float n1 = sqrtf(u0 * u0 + u1 * u1 + u2 * u2);
    split_store(g_chi, g_clo, (size_t)a * 256 + f, q[i], q[i + 1]);
    split_store(g_chi, g_clo, (size_t)a * 256 + 128 + f, n0, n1);
}

__global__ void update_kernel(float* __restrict__ q, float* __restrict__ mu) {
    int i = (blockIdx.x * blockDim.x + threadIdx.x) * 2;
    if (i >= NA * FF) return;
    int a = i >> 7, f = i & 127;
    float s0 = 0.0f, s1 = 0.0f;
    float xmu0 = g_x[a * 384 + 128 + f], xmu1 = g_x[a * 384 + 128 + f + 1];
#pragma unroll
    for (int d = 0; d < 3; d++) {
        float mv0 = g_mumix[(a * 3 + d) * 256 + f];
        float mw0 = g_mumix[(a * 3 + d) * 256 + 128 + f];
        float mv1 = g_mumix[(a * 3 + d) * 256 + f + 1];
        float mw1 = g_mumix[(a * 3 + d) * 256 + 128 + f + 1];
        s0 += mv0 * mw0;
        s1 += mv1 * mw1;
        mu[a * 384 + d * 128 + f] += xmu0 * mw0;
        mu[a * 384 + d * 128 + f + 1] += xmu1 * mw1;
    }
    float q0 = q[i] + g_x[a * 384 + f] + g_x[a * 384 + 256 + f] * s0;
    float q1 = q[i + 1] + g_x[a * 384 + f + 1] + g_x[a * 384 + 256 + f + 1] * s1;
    q[i] = q0;
    q[i + 1] = q1;
    split_store(g_qhi, g_qlo, i, q0, q1);
}

// =================== launcher ===================
extern "C" void kernel_launch(void* const* d_in, const int* in_sizes, int n_in,
                              void* d_out, int out_size) {
    const float* r_ij      = (const float*)d_in[0];
    const float* embedding = (const float*)d_in[1];
    const float* filt_W    = (const float*)d_in[2];
    const float* filt_b    = (const float*)d_in[3];
    const float* inter_W1  = (const float*)d_in[4];
    const float* inter_b1  = (const float*)d_in[5];
    const float* inter_W2  = (const float*)d_in[6];
    const float* inter_b2  = (const float*)d_in[7];
    const float* mix_W     = (const float*)d_in[8];
    const float* mix_b     = (const float*)d_in[9];
    const float* intra_W1  = (const float*)d_in[10];
    const float* intra_b1  = (const float*)d_in[11];
    const float* intra_W2  = (const float*)d_in[12];
    const float* intra_b2  = (const float*)d_in[13];
    const int*   z         = (const int*)d_in[14];
    const int*   idx_i     = (const int*)d_in[15];
    const int*   idx_j     = (const int*)d_in[16];

    float* q  = (float*)d_out;
    float* mu = q + (size_t)NA * FF;

    void *p_x, *p_mumix, *p_qhi, *p_qlo, *p_hhi, *p_hlo, *p_muhi, *p_mulo, *p_chi, *p_clo,
        *p_Bhi, *p_Blo, *p_FWh, *p_FWl, *p_phh, *p_phl, *p_filt, *p_zeros;
    cudaGetSymbolAddress(&p_x, g_x);
    cudaGetSymbolAddress(&p_mumix, g_mumix);
    cudaGetSymbolAddress(&p_qhi, g_qhi);
    cudaGetSymbolAddress(&p_qlo, g_qlo);
    cudaGetSymbolAddress(&p_hhi, g_hhi);
    cudaGetSymbolAddress(&p_hlo, g_hlo);
    cudaGetSymbolAddress(&p_muhi, g_muhi);
    cudaGetSymbolAddress(&p_mulo, g_mulo);
    cudaGetSymbolAddress(&p_chi, g_chi);
    cudaGetSymbolAddress(&p_clo, g_clo);
    cudaGetSymbolAddress(&p_Bhi, g_Bhi);
    cudaGetSymbolAddress(&p_Blo, g_Blo);
    cudaGetSymbolAddress(&p_FWh, g_FWh);
    cudaGetSymbolAddress(&p_FWl, g_FWl);
    cudaGetSymbolAddress(&p_phh, g_phh);
    cudaGetSymbolAddress(&p_phl, g_phl);
    cudaGetSymbolAddress(&p_filt, g_filt);
    cudaGetSymbolAddress(&p_zeros, g_zeros);
    float* xbuf  = (float*)p_x;
    float* mumix = (float*)p_mumix;
    float* filt  = (float*)p_filt;
    float* zeros = (float*)p_zeros;
    __nv_bfloat16 *qhi = (__nv_bfloat16*)p_qhi, *qlo = (__nv_bfloat16*)p_qlo;
    __nv_bfloat16 *hhi = (__nv_bfloat16*)p_hhi, *hlo = (__nv_bfloat16*)p_hlo;
    __nv_bfloat16 *muhi = (__nv_bfloat16*)p_muhi, *mulo = (__nv_bfloat16*)p_mulo;
    __nv_bfloat16 *chi = (__nv_bfloat16*)p_chi, *clo = (__nv_bfloat16*)p_clo;
    __nv_bfloat16 *Bhi = (__nv_bfloat16*)p_Bhi, *Blo = (__nv_bfloat16*)p_Blo;
    __nv_bfloat16 *FWh = (__nv_bfloat16*)p_FWh, *FWl = (__nv_bfloat16*)p_FWl;
    __nv_bfloat16 *phh = (__nv_bfloat16*)p_phh, *phl = (__nv_bfloat16*)p_phl;

    init_kernel<<<(NA * 384 + 255) / 256, 256>>>(z, embedding, q, mu);
    hist_kernel<<<(NE + 255) / 256, 256>>>(idx_i);
    scan_kernel<<<1, SCAN_T>>>();
    scatter_kernel<<<(NE + 255) / 256, 256>>>(idx_i, idx_j);
    geom_kernel<<<(NE + 255) / 256, 256>>>(r_ij);
    fwprep_kernel<<<(NL * 384 * 32 + 255) / 256, 256>>>(filt_W, filt_b);
    wprep_kernel<<<(NL * 128 * 128 + 255) / 256, 256>>>(inter_W1, 128, 128, 0);
    wprep_kernel<<<(NL * 128 * 384 + 255) / 256, 256>>>(inter_W2, 128, 384, 16384);
    wprep_kernel<<<(NL * 128 * 256 + 255) / 256, 256>>>(mix_W, 128, 256, 65536);
    wprep_kernel<<<(NL * 256 * 128 + 255) / 256, 256>>>(intra_W1, 256, 128, 98304);
    wprep_kernel<<<(NL * 128 * 384 + 255) / 256, 256>>>(intra_W2, 128, 384, 131072);

    for (int l = 0; l < NL; l++) {
        int wb = l * WL;
        // h = silu(q @ W1 + b1) -> split only
        gemm_mma<<<dim3(1, (NA + 127) / 128), 256>>>(
            qhi, qlo, Bhi + wb, Blo + wb, inter_b1 + l * 128,
            nullptr, hhi, hlo, NA, 128, 128, 1);
        // x = h @ W2 + b2 -> fp32
        gemm_mma<<<dim3(3, (NA + 127) / 128), 256>>>(
            hhi, hlo, Bhi + wb + 16384, Blo + wb + 16384, inter_b2 + l * 384,
            xbuf, nullptr, nullptr, NA, 384, 128, 0);
        // per-edge filters via tensor GEMM (sorted order): F = phi_pad @ FW^T
        gemm_mma<<<dim3(3, (NE + 127) / 128), 256>>>(
            phh, phl, FWh + l * 12288, FWl + l * 12288, zeros,
            filt, nullptr, nullptr, NE, 384, 32, 0);
        // edge messages: sorted chunks, register accumulation, flush-on-change
        msg_kernel<<<(NE + 127) / 128, 128>>>(filt, mu, q);
        // mu += dmu (emit mu split)
        addmu_kernel<<<(NA * 192 + 255) / 256, 256>>>(mu);
        // mu_mix = mu @ mix_W + mix_b -> fp32
        gemm_mma<<<dim3(2, (NA * 3 + 127) / 128), 256>>>(
            muhi, mulo, Bhi + wb + 65536, Blo + wb + 65536, mix_b + l * 256,
            mumix, nullptr, nullptr, NA * 3, 256, 128, 0);
        // ctx = [q, ||mu_V||] -> split only
        ctx_kernel<<<(NA * 64 + 255) / 256, 256>>>(q);
        // h = silu(ctx @ intra_W1 + b1) -> split only
        gemm_mma<<<dim3(1, (NA + 127) / 128), 256>>>(
            chi, clo, Bhi + wb + 98304, Blo + wb + 98304, intra_b1 + l * 128,
            nullptr, hhi, hlo, NA, 128, 256, 1);
        // x = h @ intra_W2 + b2 -> fp32
        gemm_mma<<<dim3(3, (NA + 127) / 128), 256>>>(
            hhi, hlo, Bhi + wb + 131072, Blo + wb + 131072, intra_b2 + l * 384,
            xbuf, nullptr, nullptr, NA, 384, 128, 0);
        // q += dq_intra + dqmu_intra (emit q split); mu += dmu_intra
        update_kernel<<<(NA * 64 + 255) / 256, 256>>>(q, mu);
    }
}

// round 17
// speedup vs baseline: 1.3980x; 1.0212x over previous
#include <cuda_runtime.h>
#include <cuda_bf16.h>
#include <math.h>
#include <stdint.h>

#define NA 15000
#define NE 300000
#define FF 128
#define NRBF 20
#define NL 3
#define CUTOFF 5.0f
#define PI_F 3.14159265358979f

// =================== static scratch ===================
__device__ float4 g_dirf[NE];                     // SORTED (dir.xyz, fcut)
__device__ __nv_bfloat16 g_phh[(size_t)NE * 32];  // SORTED padded phi hi (k20=fcut)
__device__ __nv_bfloat16 g_phl[(size_t)NE * 32];  // SORTED phi lo
__device__ float g_filt[(size_t)NE * 384];        // SORTED per-edge filters (fp32)
__device__ int g_is[NE], g_js[NE], g_perm[NE];
__device__ int g_cnt[NA], g_head[NA];
__device__ float g_x[NA * 384];
__device__ float g_mumix[NA * 3 * 256];
__device__ float g_dmu[NA * 384];
__device__ float g_zeros[384];
// bf16 hi/lo split operands
__device__ __nv_bfloat16 g_qhi[NA * 128], g_qlo[NA * 128];
__device__ __nv_bfloat16 g_hhi[NA * 128], g_hlo[NA * 128];
__device__ __nv_bfloat16 g_muhi[NA * 384], g_mulo[NA * 384];
__device__ __nv_bfloat16 g_chi[NA * 256], g_clo[NA * 256];
#define WL 180224
__device__ __nv_bfloat16 g_Bhi[NL * WL];
__device__ __nv_bfloat16 g_Blo[NL * WL];
// filter weights transposed+padded: [l][n=384][k=32]
__device__ __nv_bfloat16 g_FWh[NL * 384 * 32];
__device__ __nv_bfloat16 g_FWl[NL * 384 * 32];

__device__ __forceinline__ void split_store(__nv_bfloat16* hi, __nv_bfloat16* lo,
                                            size_t off, float v0, float v1) {
    __nv_bfloat16 h0 = __float2bfloat16(v0), h1 = __float2bfloat16(v1);
    __nv_bfloat162 H, L;
    H.x = h0; H.y = h1;
    L.x = __float2bfloat16(v0 - __bfloat162float(h0));
    L.y = __float2bfloat16(v1 - __bfloat162float(h1));
    *(__nv_bfloat162*)(hi + off) = H;
    *(__nv_bfloat162*)(lo + off) = L;
}

// =================== prep kernels ===================
__global__ void init_kernel(const int* __restrict__ z, const float* __restrict__ emb,
                            float* __restrict__ q, float* __restrict__ mu) {
    int i = blockIdx.x * blockDim.x + threadIdx.x;
    if (i >= NA * 384) return;
    mu[i] = 0.0f;
    g_dmu[i] = 0.0f;
    if (i < NA) g_cnt[i] = 0;
    if (i < NA * FF) {
        int a = i >> 7, f = i & 127;
        float v = emb[z[a] * FF + f];
        q[i] = v;
        __nv_bfloat16 h = __float2bfloat16(v);
        g_qhi[i] = h;
        g_qlo[i] = __float2bfloat16(v - __bfloat162float(h));
    }
}

__global__ void hist_kernel(const int* __restrict__ idx_i) {
    int e = blockIdx.x * blockDim.x + threadIdx.x;
    if (e < NE) atomicAdd(&g_cnt[idx_i[e]], 1);
}

#define SCAN_T 1024
#define SCAN_CH ((NA + SCAN_T - 1) / SCAN_T)
__global__ void __launch_bounds__(SCAN_T) scan_kernel() {
    __shared__ int sh[SCAN_T];
    int t = threadIdx.x;
    int start = t * SCAN_CH;
    int s = 0;
#pragma unroll
    for (int k = 0; k < SCAN_CH; k++) {
        int i = start + k;
        if (i < NA) s += g_cnt[i];
    }
    sh[t] = s;
    __syncthreads();
    for (int off = 1; off < SCAN_T; off <<= 1) {
        int v = (t >= off) ? sh[t - off] : 0;
        __syncthreads();
        sh[t] += v;
        __syncthreads();
    }
    int base = (t == 0) ? 0 : sh[t - 1];
#pragma unroll
    for (int k = 0; k < SCAN_CH; k++) {
        int i = start + k;
        if (i < NA) {
            g_head[i] = base;
            base += g_cnt[i];
        }
    }
}

__global__ void scatter_kernel(const int* __restrict__ idx_i, const int* __restrict__ idx_j) {
    int e = blockIdx.x * blockDim.x + threadIdx.x;
    if (e >= NE) return;
    int i = idx_i[e];
    int pos = atomicAdd(&g_head[i], 1);
    g_perm[e] = pos;
    g_is[pos] = i;
    g_js[pos] = idx_j[e];
}

// geometry written at SORTED positions: dirf + padded split phi (k20 = fcut = bias row)
__global__ void geom_kernel(const float* __restrict__ rij) {
    int e = blockIdx.x * blockDim.x + threadIdx.x;
    if (e >= NE) return;
    int p = g_perm[e];
    float r0 = rij[e * 3 + 0], r1 = rij[e * 3 + 1], r2 = rij[e * 3 + 2];
    float d = sqrtf(r0 * r0 + r1 * r1 + r2 * r2);
    float inv = 1.0f / d;
    float fc = (d < CUTOFF) ? 0.5f * (cosf(d * PI_F / CUTOFF) + 1.0f) : 0.0f;
    g_dirf[p] = make_float4(r0 * inv, r1 * inv, r2 * inv, fc);
    const float width = CUTOFF / (NRBF - 1);
    const float coeff = -0.5f / (width * width);
    __nv_bfloat16* ph = g_phh + (size_t)p * 32;
    __nv_bfloat16* pl = g_phl + (size_t)p * 32;
#pragma unroll
    for (int k = 0; k < 32; k++) {
        float v;
        if (k < NRBF) {
            float t = d - width * k;
            v = expf(coeff * t * t) * fc;
        } else if (k == NRBF) {
            v = fc;
        } else {
            v = 0.0f;
        }
        __nv_bfloat16 h = __float2bfloat16(v);
        ph[k] = h;
        pl[k] = __float2bfloat16(v - __bfloat162float(h));
    }
}

__global__ void fwprep_kernel(const float* __restrict__ W, const float* __restrict__ b) {
    int i = blockIdx.x * blockDim.x + threadIdx.x;
    if (i >= NL * 384 * 32) return;
    int l = i / (384 * 32), r = i % (384 * 32);
    int n = r >> 5, k = r & 31;
    float v = 0.0f;
    if (k < NRBF) v = W[k * (NL * 384) + l * 384 + n];
    else if (k == NRBF) v = b[l * 384 + n];
    __nv_bfloat16 h = __float2bfloat16(v);
    g_FWh[i] = h;
    g_FWl[i] = __float2bfloat16(v - __bfloat162float(h));
}

// batched transpose+split of all five GEMM weight groups, all layers, one launch
__global__ void wprep_all(const float* __restrict__ w1, const float* __restrict__ w2,
                          const float* __restrict__ mixw, const float* __restrict__ iw1,
                          const float* __restrict__ iw2) {
    int i = blockIdx.x * blockDim.x + threadIdx.x;
    if (i >= NL * WL) return;
    int l = i / WL, r = i % WL;
    const float* src;
    int K, N, off;
    if (r < 16384)       { src = w1;   K = 128; N = 128; off = r; }
    else if (r < 65536)  { src = w2;   K = 128; N = 384; off = r - 16384; }
    else if (r < 98304)  { src = mixw; K = 128; N = 256; off = r - 65536; }
    else if (r < 131072) { src = iw1;  K = 256; N = 128; off = r - 98304; }
    else                 { src = iw2;  K = 128; N = 384; off = r - 131072; }
    int n = off / K, k = off % K;
    float v = src[(size_t)l * K * N + (size_t)k * N + n];
    __nv_bfloat16 h = __float2bfloat16(v);
    g_Bhi[i] = h;
    g_Blo[i] = __float2bfloat16(v - __bfloat162float(h));
}

// =================== mma helpers ===================
__device__ __forceinline__ void ldm_x4(uint32_t* r, uint32_t addr) {
    asm volatile("ldmatrix.sync.aligned.m8n8.x4.shared.b16 {%0,%1,%2,%3}, [%4];"
                 : "=r"(r[0]), "=r"(r[1]), "=r"(r[2]), "=r"(r[3]) : "r"(addr));
}
__device__ __forceinline__ void ldm_x2(uint32_t* r, uint32_t addr) {
    asm volatile("ldmatrix.sync.aligned.m8n8.x2.shared.b16 {%0,%1}, [%2];"
                 : "=r"(r[0]), "=r"(r[1]) : "r"(addr));
}
__device__ __forceinline__ void mma_bf16(float* d, const uint32_t* a, const uint32_t* b) {
    asm volatile(
        "mma.sync.aligned.m16n8k16.row.col.f32.bf16.bf16.f32 "
        "{%0,%1,%2,%3}, {%4,%5,%6,%7}, {%8,%9}, {%0,%1,%2,%3};"
        : "+f"(d[0]), "+f"(d[1]), "+f"(d[2]), "+f"(d[3])
        : "r"(a[0]), "r"(a[1]), "r"(a[2]), "r"(a[3]), "r"(b[0]), "r"(b[1]));
}
__device__ __forceinline__ uint32_t smem_u32(const void* p) {
    uint32_t a;
    asm("{ .reg .u64 t; cvta.to.shared.u64 t, %1; cvt.u32.u64 %0, t; }" : "=r"(a) : "l"(p));
    return a;
}

// =================== bf16x3 GEMM body (virtual block coords, smem pointers) ===================
#define AS 40
__device__ __forceinline__ void gemm_body(const __nv_bfloat16* __restrict__ Ahi,
                                          const __nv_bfloat16* __restrict__ Alo,
                                          const __nv_bfloat16* __restrict__ Bhi,
                                          const __nv_bfloat16* __restrict__ Blo,
                                          const float* __restrict__ bias,
                                          float* __restrict__ C,
                                          __nv_bfloat16* __restrict__ Shi,
                                          __nv_bfloat16* __restrict__ Slo,
                                          int M, int N, int K, int act, int bx, int by,
                                          __nv_bfloat16* sAh, __nv_bfloat16* sAl,
                                          __nv_bfloat16* sBh, __nv_bfloat16* sBl) {
    int tid = threadIdx.x;
    int wid = tid >> 5, lane = tid & 31;
    int wm = wid & 3, wn = wid >> 2;
    int row0 = by * 128, col0 = bx * 128;

    float acc[2][8][4];
#pragma unroll
    for (int i = 0; i < 2; i++)
#pragma unroll
        for (int j = 0; j < 8; j++)
#pragma unroll
            for (int k = 0; k < 4; k++) acc[i][j][k] = 0.f;

    int lrow = tid >> 1, lcol = (tid & 1) << 4;
    bool rowok = (row0 + lrow) < M;
    const __nv_bfloat16* pAh = Ahi + (size_t)(row0 + lrow) * K + lcol;
    const __nv_bfloat16* pAl = Alo + (size_t)(row0 + lrow) * K + lcol;
    const __nv_bfloat16* pBh = Bhi + (size_t)(col0 + lrow) * K + lcol;
    const __nv_bfloat16* pBl = Blo + (size_t)(col0 + lrow) * K + lcol;
    const uint4 z4 = make_uint4(0, 0, 0, 0);

    uint32_t aAh = smem_u32(sAh + wm * 32 * AS);
    uint32_t aAl = smem_u32(sAl + wm * 32 * AS);
    uint32_t aBh = smem_u32(sBh + wn * 64 * AS);
    uint32_t aBl = smem_u32(sBl + wn * 64 * AS);

    for (int c = 0; c < (K >> 5); c++) {
#pragma unroll
        for (int u = 0; u < 2; u++) {
            int co = c * 32 + u * 8;
            *(uint4*)(sAh + lrow * AS + lcol + u * 8) = rowok ? *(const uint4*)(pAh + co) : z4;
            *(uint4*)(sAl + lrow * AS + lcol + u * 8) = rowok ? *(const uint4*)(pAl + co) : z4;
            *(uint4*)(sBh + lrow * AS + lcol + u * 8) = *(const uint4*)(pBh + co);
            *(uint4*)(sBl + lrow * AS + lcol + u * 8) = *(const uint4*)(pBl + co);
        }
        __syncthreads();
#pragma unroll
        for (int ks = 0; ks < 2; ks++) {
            int kk = ks * 16;
            uint32_t ah[2][4], al[2][4];
            uint32_t aoff = ((lane & 15) * AS + kk + ((lane >> 4) << 3)) * 2;
#pragma unroll
            for (int mt = 0; mt < 2; mt++) {
                ldm_x4(ah[mt], aAh + mt * 16 * AS * 2 + aoff);
                ldm_x4(al[mt], aAl + mt * 16 * AS * 2 + aoff);
            }
            uint32_t boff = ((lane & 7) * AS + kk + (((lane >> 3) & 1) << 3)) * 2;
#pragma unroll
            for (int nt = 0; nt < 8; nt++) {
                uint32_t bh[2], bl[2];
                ldm_x2(bh, aBh + nt * 8 * AS * 2 + boff);
                ldm_x2(bl, aBl + nt * 8 * AS * 2 + boff);
#pragma unroll
                for (int mt = 0; mt < 2; mt++) {
                    mma_bf16(acc[mt][nt], ah[mt], bh);
                    mma_bf16(acc[mt][nt], ah[mt], bl);
                    mma_bf16(acc[mt][nt], al[mt], bh);
                }
            }
        }
        __syncthreads();
    }

    int gid = lane >> 2, tig = lane & 3;
#pragma unroll
    for (int mt = 0; mt < 2; mt++) {
#pragma unroll
        for (int nt = 0; nt < 8; nt++) {
            int cc = col0 + wn * 64 + nt * 8 + tig * 2;
            float b0 = __ldg(bias + cc), b1 = __ldg(bias + cc + 1);
            int r0 = row0 + wm * 32 + mt * 16 + gid;
            float v0 = acc[mt][nt][0] + b0, v1 = acc[mt][nt][1] + b1;
            float v2 = acc[mt][nt][2] + b0, v3 = acc[mt][nt][3] + b1;
            if (act) {
                v0 = v0 / (1.0f + expf(-v0));
                v1 = v1 / (1.0f + expf(-v1));
                v2 = v2 / (1.0f + expf(-v2));
                v3 = v3 / (1.0f + expf(-v3));
            }
            if (r0 < M) {
                size_t o = (size_t)r0 * N + cc;
                if (C) *(float2*)(C + o) = make_float2(v0, v1);
                if (Shi) split_store(Shi, Slo, o, v0, v1);
            }
            if (r0 + 8 < M) {
                size_t o = (size_t)(r0 + 8) * N + cc;
                if (C) *(float2*)(C + o) = make_float2(v2, v3);
                if (Shi) split_store(Shi, Slo, o, v2, v3);
            }
        }
    }
}

__global__ void __launch_bounds__(256) gemm_mma(const __nv_bfloat16* __restrict__ Ahi,
                                                const __nv_bfloat16* __restrict__ Alo,
                                                const __nv_bfloat16* __restrict__ Bhi,
                                                const __nv_bfloat16* __restrict__ Blo,
                                                const float* __restrict__ bias,
                                                float* __restrict__ C,
                                                __nv_bfloat16* __restrict__ Shi,
                                                __nv_bfloat16* __restrict__ Slo,
                                                int M, int N, int K, int act) {
    __shared__ __nv_bfloat16 sAh[128 * AS], sAl[128 * AS], sBh[128 * AS], sBl[128 * AS];
    gemm_body(Ahi, Alo, Bhi, Blo, bias, C, Shi, Slo, M, N, K, act,
              blockIdx.x, blockIdx.y, sAh, sAl, sBh, sBl);
}

// dual-grid: side A (filter GEMM, by < splitY) runs concurrently with side B (h GEMM).
__global__ void __launch_bounds__(256) gemm_dual(
    const __nv_bfloat16* Ahi1, const __nv_bfloat16* Alo1,
    const __nv_bfloat16* Bhi1, const __nv_bfloat16* Blo1,
    const float* bias1, float* C1, int M1, int N1, int K1, int act1,
    const __nv_bfloat16* Ahi2, const __nv_bfloat16* Alo2,
    const __nv_bfloat16* Bhi2, const __nv_bfloat16* Blo2,
    const float* bias2, __nv_bfloat16* Shi2, __nv_bfloat16* Slo2,
    int M2, int N2, int K2, int act2,
    int splitY, int bxB) {
    __shared__ __nv_bfloat16 sAh[128 * AS], sAl[128 * AS], sBh[128 * AS], sBl[128 * AS];
    int by = blockIdx.y;
    if (by < splitY) {
        gemm_body(Ahi1, Alo1, Bhi1, Blo1, bias1, C1, nullptr, nullptr,
                  M1, N1, K1, act1, blockIdx.x, by, sAh, sAl, sBh, sBl);
    } else {
        if ((int)blockIdx.x >= bxB) return;
        gemm_body(Ahi2, Alo2, Bhi2, Blo2, bias2, nullptr, Shi2, Slo2,
                  M2, N2, K2, act2, blockIdx.x, by - splitY, sAh, sAl, sBh, sBl);
    }
}

// =================== message kernel (sorted chunks, register accumulation) ===================
__global__ void __launch_bounds__(128) msg_kernel(const float* __restrict__ F,
                                                  const float* __restrict__ mu,
                                                  float* __restrict__ q) {
    int f = threadIdx.x;
    int base = blockIdx.x * 128;
    int eend = min(base + 128, NE);
    float aq = 0.f, a0 = 0.f, a1 = 0.f, a2 = 0.f;
    int curi = -1;
#pragma unroll 2
    for (int e = base; e < eend; e++) {
        int i = __ldg(g_is + e);
        if (i != curi) {
            if (curi >= 0) {
                atomicAdd(q + curi * 128 + f, aq);
                atomicAdd(g_dmu + curi * 384 + f, a0);
                atomicAdd(g_dmu + curi * 384 + 128 + f, a1);
                atomicAdd(g_dmu + curi * 384 + 256 + f, a2);
            }
            curi = i;
            aq = a0 = a1 = a2 = 0.f;
        }
        int j = __ldg(g_js + e);
        const float* Fe = F + (size_t)e * 384;
        float F0 = __ldg(Fe + f), F1 = __ldg(Fe + 128 + f), F2 = __ldg(Fe + 256 + f);
        float4 df = __ldg(g_dirf + e);
        const float* xj = g_x + j * 384;
        const float* mj = mu + j * 384;
        float dmuR = F1 * __ldg(xj + 128 + f);
        float dmm  = F2 * __ldg(xj + 256 + f);
        aq += F0 * __ldg(xj + f);
        a0 += dmuR * df.x + dmm * __ldg(mj + f);
        a1 += dmuR * df.y + dmm * __ldg(mj + 128 + f);
        a2 += dmuR * df.z + dmm * __ldg(mj + 256 + f);
    }
    if (curi >= 0) {
        atomicAdd(q + curi * 128 + f, aq);
        atomicAdd(g_dmu + curi * 384 + f, a0);
        atomicAdd(g_dmu + curi * 384 + 128 + f, a1);
        atomicAdd(g_dmu + curi * 384 + 256 + f, a2);
    }
}

// mu += dmu; dmu = 0; emit mu hi/lo split
__global__ void addmu_kernel(float* __restrict__ mu) {
    int i = (blockIdx.x * blockDim.x + threadIdx.x) * 2;
    if (i >= NA * 384) return;
    float v0 = mu[i] + g_dmu[i];
    float v1 = mu[i + 1] + g_dmu[i + 1];
    mu[i] = v0;
    mu[i + 1] = v1;
    g_dmu[i] = 0.0f;
    g_dmu[i + 1] = 0.0f;
    split_store(g_muhi, g_mulo, i, v0, v1);
}

// =================== ctx / update ===================
__global__ void ctx_kernel(const float* __restrict__ q) {
    int i = (blockIdx.x * blockDim.x + threadIdx.x) * 2;
    if (i >= NA * FF) return;
    int a = i >> 7, f = i & 127;
    float v0 = g_mumix[(a * 3 + 0) * 256 + f];
    float v1 = g_mumix[(a * 3 + 1) * 256 + f];
    float v2 = g_mumix[(a * 3 + 2) * 256 + f];
    float n0 = sqrtf(v0 * v0 + v1 * v1 + v2 * v2);
    float u0 = g_mumix[(a * 3 + 0) * 256 + f + 1];
    float u1 = g_mumix[(a * 3 + 1) * 256 + f + 1];
    float u2 = g_mumix[(a * 3 + 2) * 256 + f + 1];
    float n1 = sqrtf(u0 * u0 + u1 * u1 + u2 * u2);
    split_store(g_chi, g_clo, (size_t)a * 256 + f, q[i], q[i + 1]);
    split_store(g_chi, g_clo, (size_t)a * 256 + 128 + f, n0, n1);
}

__global__ void update_kernel(float* __restrict__ q, float* __restrict__ mu) {
    int i = (blockIdx.x * blockDim.x + threadIdx.x) * 2;
    if (i >= NA * FF) return;
    int a = i >> 7, f = i & 127;
    float s0 = 0.0f, s1 = 0.0f;
    float xmu0 = g_x[a * 384 + 128 + f], xmu1 = g_x[a * 384 + 128 + f + 1];
#pragma unroll
    for (int d = 0; d < 3; d++) {
        float mv0 = g_mumix[(a * 3 + d) * 256 + f];
        float mw0 = g_mumix[(a * 3 + d) * 256 + 128 + f];
        float mv1 = g_mumix[(a * 3 + d) * 256 + f + 1];
        float mw1 = g_mumix[(a * 3 + d) * 256 + 128 + f + 1];
        s0 += mv0 * mw0;
        s1 += mv1 * mw1;
        mu[a * 384 + d * 128 + f] += xmu0 * mw0;
        mu[a * 384 + d * 128 + f + 1] += xmu1 * mw1;
    }
    float q0 = q[i] + g_x[a * 384 + f] + g_x[a * 384 + 256 + f] * s0;
    float q1 = q[i + 1] + g_x[a * 384 + f + 1] + g_x[a * 384 + 256 + f + 1] * s1;
    q[i] = q0;
    q[i + 1] = q1;
    split_store(g_qhi, g_qlo, i, q0, q1);
}

// =================== launcher ===================
extern "C" void kernel_launch(void* const* d_in, const int* in_sizes, int n_in,
                              void* d_out, int out_size) {
    const float* r_ij      = (const float*)d_in[0];
    const float* embedding = (const float*)d_in[1];
    const float* filt_W    = (const float*)d_in[2];
    const float* filt_b    = (const float*)d_in[3];
    const float* inter_W1  = (const float*)d_in[4];
    const float* inter_b1  = (const float*)d_in[5];
    const float* inter_W2  = (const float*)d_in[6];
    const float* inter_b2  = (const float*)d_in[7];
    const float* mix_W     = (const float*)d_in[8];
    const float* mix_b     = (const float*)d_in[9];
    const float* intra_W1  = (const float*)d_in[10];
    const float* intra_b1  = (const float*)d_in[11];
    const float* intra_W2  = (const float*)d_in[12];
    const float* intra_b2  = (const float*)d_in[13];
    const int*   z         = (const int*)d_in[14];
    const int*   idx_i     = (const int*)d_in[15];
    const int*   idx_j     = (const int*)d_in[16];

    float* q  = (float*)d_out;
    float* mu = q + (size_t)NA * FF;

    void *p_x, *p_mumix, *p_qhi, *p_qlo, *p_hhi, *p_hlo, *p_muhi, *p_mulo, *p_chi, *p_clo,
        *p_Bhi, *p_Blo, *p_FWh, *p_FWl, *p_phh, *p_phl, *p_filt, *p_zeros;
    cudaGetSymbolAddress(&p_x, g_x);
    cudaGetSymbolAddress(&p_mumix, g_mumix);
    cudaGetSymbolAddress(&p_qhi, g_qhi);
    cudaGetSymbolAddress(&p_qlo, g_qlo);
    cudaGetSymbolAddress(&p_hhi, g_hhi);
    cudaGetSymbolAddress(&p_hlo, g_hlo);
    cudaGetSymbolAddress(&p_muhi, g_muhi);
    cudaGetSymbolAddress(&p_mulo, g_mulo);
    cudaGetSymbolAddress(&p_chi, g_chi);
    cudaGetSymbolAddress(&p_clo, g_clo);
    cudaGetSymbolAddress(&p_Bhi, g_Bhi);
    cudaGetSymbolAddress(&p_Blo, g_Blo);
    cudaGetSymbolAddress(&p_FWh, g_FWh);
    cudaGetSymbolAddress(&p_FWl, g_FWl);
    cudaGetSymbolAddress(&p_phh, g_phh);
    cudaGetSymbolAddress(&p_phl, g_phl);
    cudaGetSymbolAddress(&p_filt, g_filt);
    cudaGetSymbolAddress(&p_zeros, g_zeros);
    float* xbuf  = (float*)p_x;
    float* mumix = (float*)p_mumix;
    float* filt  = (float*)p_filt;
    float* zeros = (float*)p_zeros;
    __nv_bfloat16 *qhi = (__nv_bfloat16*)p_qhi, *qlo = (__nv_bfloat16*)p_qlo;
    __nv_bfloat16 *hhi = (__nv_bfloat16*)p_hhi, *hlo = (__nv_bfloat16*)p_hlo;
    __nv_bfloat16 *muhi = (__nv_bfloat16*)p_muhi, *mulo = (__nv_bfloat16*)p_mulo;
    __nv_bfloat16 *chi = (__nv_bfloat16*)p_chi, *clo = (__nv_bfloat16*)p_clo;
    __nv_bfloat16 *Bhi = (__nv_bfloat16*)p_Bhi, *Blo = (__nv_bfloat16*)p_Blo;
    __nv_bfloat16 *FWh = (__nv_bfloat16*)p_FWh, *FWl = (__nv_bfloat16*)p_FWl;
    __nv_bfloat16 *phh = (__nv_bfloat16*)p_phh, *phl = (__nv_bfloat16*)p_phl;

    const int NEB = (NE + 127) / 128;  // 2344 edge row-blocks
    const int NAB = (NA + 127) / 128;  // 118 atom row-blocks

    init_kernel<<<(NA * 384 + 255) / 256, 256>>>(z, embedding, q, mu);
    hist_kernel<<<(NE + 255) / 256, 256>>>(idx_i);
    scan_kernel<<<1, SCAN_T>>>();
    scatter_kernel<<<(NE + 255) / 256, 256>>>(idx_i, idx_j);
    geom_kernel<<<(NE + 255) / 256, 256>>>(r_ij);
    fwprep_kernel<<<(NL * 384 * 32 + 255) / 256, 256>>>(filt_W, filt_b);
    wprep_all<<<(NL * WL + 255) / 256, 256>>>(inter_W1, inter_W2, mix_W, intra_W1, intra_W2);

    for (int l = 0; l < NL; l++) {
        int wb = l * WL;
        // DUAL: filter GEMM (F = phi_pad @ FW^T, fp32 out) || h1 = silu(q @ W1 + b1) (split out)
        gemm_dual<<<dim3(3, NEB + NAB), 256>>>(
            phh, phl, FWh + l * 12288, FWl + l * 12288, zeros, filt, NE, 384, 32, 0,
            qhi, qlo, Bhi + wb, Blo + wb, inter_b1 + l * 128, hhi, hlo, NA, 128, 128, 1,
            NEB, 1);
        // x = h @ W2 + b2 -> fp32
        gemm_mma<<<dim3(3, NAB), 256>>>(
            hhi, hlo, Bhi + wb + 16384, Blo + wb + 16384, inter_b2 + l * 384,
            xbuf, nullptr, nullptr, NA, 384, 128, 0);
        // edge messages: sorted chunks, register accumulation, flush-on-change
        msg_kernel<<<NEB, 128>>>(filt, mu, q);
        // mu += dmu (emit mu split)
        addmu_kernel<<<(NA * 192 + 255) / 256, 256>>>(mu);
        // mu_mix = mu @ mix_W + mix_b -> fp32
        gemm_mma<<<dim3(2, (NA * 3 + 127) / 128), 256>>>(
            muhi, mulo, Bhi + wb + 65536, Blo + wb + 65536, mix_b + l * 256,
            mumix, nullptr, nullptr, NA * 3, 256, 128, 0);
        // ctx = [q, ||mu_V||] -> split only
        ctx_kernel<<<(NA * 64 + 255) / 256, 256>>>(q);
        // h = silu(ctx @ intra_W1 + b1) -> split only
        gemm_mma<<<dim3(1, NAB), 256>>>(
            chi, clo, Bhi + wb + 98304, Blo + wb + 98304, intra_b1 + l * 128,
            nullptr, hhi, hlo, NA, 128, 256, 1);
        // x = h @ intra_W2 + b2 -> fp32
        gemm_mma<<<dim3(3, NAB), 256>>>(
            hhi, hlo, Bhi + wb + 131072, Blo + wb + 131072, intra_b2 + l * 384,
            xbuf, nullptr, nullptr, NA, 384, 128, 0);
        // q += dq_intra + dqmu_intra (emit q split); mu += dmu_intra
        update_kernel<<<(NA * 64 + 255) / 256, 256>>>(q, mu);
    }
}